// round 5
// baseline (speedup 1.0000x reference)
#include <cuda_runtime.h>
#include <cuda_bf16.h>
#include <cstdint>
#include <cstddef>

#define B_   8
#define H_   32
#define F_   8
#define X_   128
#define T_   256
#define TM1  255
#define BT_  2040   // B_*TM1

typedef unsigned long long ull;

// ---------- packed f32x2 helpers (FFMA2 only reachable via PTX) ----------
__device__ __forceinline__ ull pack2(float x, float y) {
    ull r; asm("mov.b64 %0,{%1,%2};" : "=l"(r) : "f"(x), "f"(y)); return r;
}
__device__ __forceinline__ void unpack2(ull v, float& x, float& y) {
    asm("mov.b64 {%0,%1},%2;" : "=f"(x), "=f"(y) : "l"(v));
}
__device__ __forceinline__ ull fma2(ull a, ull b, ull c) {
    ull r; asm("fma.rn.f32x2 %0,%1,%2,%3;" : "=l"(r) : "l"(a), "l"(b), "l"(c)); return r;
}

// ---------- static scratch ----------
__device__ __align__(16) float  d_G2[B_ * H_ * F_ * X_];          // [b][c][f][x]
__device__ __align__(16) float2 d_D[X_ * X_];                     // [k][x] fwd twiddles
__device__ __align__(16) float2 d_E[X_ * X_];                     // [k][x] inv twiddles (1/128)
__device__ __align__(16) float2 d_dX[(size_t)X_ * TM1 * B_ * H_]; // [k][t][b][c]
__device__ __align__(16) float2 d_zinit[X_ * B_ * H_];            // [k][b][i]
__device__ __align__(16) float  d_Mre[(size_t)X_ * BT_ * 1024];   // [x][m=b*255+t][i*32+j]
__device__ __align__(16) float  d_Mim[(size_t)X_ * BT_ * 1024];
__device__ __align__(16) float  d_zr[(size_t)B_ * H_ * X_ * T_];  // [b][i][k][t] re plane
__device__ __align__(16) float  d_zi[(size_t)B_ * H_ * X_ * T_];  // [b][i][k][t] im plane

// shifted-fwd: S[k] = sum_x h[x] (-1)^x e^{-2pi i k x/128}
// inverse:     u[x] = (1/128)(-1)^x sum_k Re( z[k] e^{+2pi i k x/128} )
__global__ void k_twiddle() {
    int k = blockIdx.x, x = threadIdx.x;
    float s, c;
    sincospif((float)(k * x) * (1.0f / 64.0f), &s, &c);
    float sg = (x & 1) ? -1.0f : 1.0f;
    d_D[k * X_ + x] = make_float2(sg * c, -sg * s);
    d_E[k * X_ + x] = make_float2(sg * c * (1.0f / 128.0f), sg * s * (1.0f / 128.0f));
}

// G2[b][c][f][x] = sum_h Gw[c][f][h] * z0[b][h][x]
__global__ void k_g2(const float* __restrict__ z0, const float* __restrict__ Gw) {
    int idx = blockIdx.x * blockDim.x + threadIdx.x;
    int x = idx & 127, f = (idx >> 7) & 7, c = (idx >> 10) & 31, b = idx >> 15;
    const float* gw = Gw + (c * F_ + f) * H_;
    const float* zp = z0 + b * H_ * X_ + x;
    float acc = 0.0f;
#pragma unroll
    for (int h = 0; h < H_; h++) acc += gw[h] * zp[h * X_];
    d_G2[idx] = acc;
}

// z_init[k][b][i] = shifted-DFT_x( z0[b][i][:] )
__global__ void k_zinit(const float* __restrict__ z0) {
    int b = blockIdx.x >> 5, i = blockIdx.x & 31, k = threadIdx.x;
    const float* zp = z0 + (b * H_ + i) * X_;
    const ull* Dr = (const ull*)d_D + k * X_;
    ull acc = 0;
#pragma unroll 4
    for (int x = 0; x < X_; x++) {
        float h = zp[x];
        acc = fma2(pack2(h, h), Dr[x], acc);
    }
    float2 r; unpack2(acc, r.x, r.y);
    d_zinit[(k * B_ + b) * H_ + i] = r;
}

// dX[k][t][b][ch] = DFTshift_x( sum_f G2[b][ch][f][x]*(xi[...t+1]-xi[...t]) )
// smem-resident D (padded stride 133), pre-packed (h,h) (stride 129).
// 256 thr: tq=tid&7 (t fast), kq=tid>>3; thread computes k=kq*4+c (c<4),
// t=t0+tq+8*s (s<8) -> 32 outputs, 32 fma2 per x-iter vs 12 LDS64.
#define SDX_D   0
#define SDX_HH  (128 * 133)
#define SDX_G   (SDX_HH + 64 * 129)
#define SDX_ULL (SDX_G + 512)           // sG: 1024 floats = 512 ull
__global__ void __launch_bounds__(256) k_dX(const float* __restrict__ xi) {
    extern __shared__ ull sm[];
    ull* sD  = sm + SDX_D;              // [k][x] stride 133
    ull* sHH = sm + SDX_HH;             // [t][x] stride 129, value pack2(h,h)
    float* sG = (float*)(sm + SDX_G);   // [f][x]
    int tid = threadIdx.x;
    int t0 = blockIdx.x * 64;
    int b = blockIdx.y >> 5, ch = blockIdx.y & 31;
    int tn = min(64, TM1 - t0);

    // stage twiddles
    const ull* pD = (const ull*)d_D;
    for (int e = tid; e < 128 * 128; e += 256) {
        int k = e >> 7, x = e & 127;
        sD[k * 133 + x] = pD[e];
    }
    for (int e = tid; e < F_ * X_; e += 256)
        sG[e] = d_G2[(b * H_ + ch) * F_ * X_ + e];
    __syncthreads();

    // phase A: h[x][t] = sum_f G2*(xi[t+1]-xi[t]), staged as pack2(h,h)
    for (int e = tid; e < X_ * 64; e += 256) {
        int x = e >> 6, t = e & 63;
        float acc = 0.0f;
        if (t < tn) {
#pragma unroll
            for (int f = 0; f < F_; f++) {
                const float* xp = xi + (((size_t)(b * F_ + f) * X_ + x) * T_) + t0 + t;
                acc += sG[f * X_ + x] * (xp[1] - xp[0]);
            }
        }
        sHH[t * 129 + x] = pack2(acc, acc);
    }
    __syncthreads();

    // phase B: register-tiled DFT
    int tq = tid & 7, kq = tid >> 3;
    ull acc[4][8];
#pragma unroll
    for (int c = 0; c < 4; c++)
#pragma unroll
        for (int s = 0; s < 8; s++) acc[c][s] = 0;

#pragma unroll 2
    for (int x = 0; x < X_; x++) {
        ull dv[4];
#pragma unroll
        for (int c = 0; c < 4; c++) dv[c] = sD[(kq * 4 + c) * 133 + x];
#pragma unroll
        for (int s = 0; s < 8; s++) {
            ull hh = sHH[(tq + 8 * s) * 129 + x];
#pragma unroll
            for (int c = 0; c < 4; c++) acc[c][s] = fma2(hh, dv[c], acc[c][s]);
        }
    }

#pragma unroll
    for (int c = 0; c < 4; c++) {
        int k = kq * 4 + c;
#pragma unroll
        for (int s = 0; s < 8; s++) {
            int t = t0 + tq + 8 * s;
            if (t >= TM1) continue;
            float re, im; unpack2(acc[c][s], re, im);
            d_dX[((size_t)(k * TM1 + t) * B_ + b) * H_ + ch] = make_float2(re, im);
        }
    }
}

// Meff[x][m][i*32+j] = sum_c dx[b,x,t,c]*W[x,i,c,j] (complex), m=b*255+t.
// GEMM per x: M=2040, N=1024, K=32. Pre-packed smem operands; 64m x 64n tile.
__global__ void __launch_bounds__(256) k_meff(const float* __restrict__ Wr,
                                              const float* __restrict__ Wi) {
    extern __shared__ ull sm[];
    ull* s_ar = sm;            // [k][m] pack2(dr,dr)
    ull* s_ai = sm + 2048;     // [k][m] pack2(di,di)
    ull* s_w1 = sm + 4096;     // [k][n] pack2(Wr,Wi)
    ull* s_w2 = sm + 6144;     // [k][n] pack2(-Wi,Wr)
    int tid = threadIdx.x;
    int x  = blockIdx.z;
    int m0 = blockIdx.y * 64;
    int n0 = blockIdx.x * 64;

    for (int e = tid; e < 2048; e += 256) {
        int ml = e >> 5, kk = e & 31;
        int m = m0 + ml;
        float2 v = make_float2(0.0f, 0.0f);
        if (m < BT_) {
            int bb = m / TM1, tt = m - bb * TM1;
            v = d_dX[((size_t)(x * TM1 + tt) * B_ + bb) * H_ + kk];
        }
        s_ar[kk * 64 + ml] = pack2(v.x, v.x);
        s_ai[kk * 64 + ml] = pack2(v.y, v.y);
    }
    for (int e = tid; e < 2048; e += 256) {
        int kk = e >> 6, nn = e & 63;
        int n = n0 + nn;
        int i = n >> 5, j = n & 31;
        size_t g = (((size_t)x * H_ + i) * H_ + kk) * H_ + j;
        float wr = Wr[g], wi = Wi[g];
        s_w1[kk * 64 + nn] = pack2(wr, wi);
        s_w2[kk * 64 + nn] = pack2(-wi, wr);
    }
    __syncthreads();

    int tx = tid & 15, ty = tid >> 4;
    int mb = ty * 4;
    ull acc[4][4];
#pragma unroll
    for (int mm = 0; mm < 4; mm++)
#pragma unroll
        for (int nn = 0; nn < 4; nn++) acc[mm][nn] = 0;

#pragma unroll 4
    for (int kk = 0; kk < 32; kk++) {
        ull dur[4], dui[4];
#pragma unroll
        for (int mm = 0; mm < 4; mm++) {
            dur[mm] = s_ar[kk * 64 + mb + mm];
            dui[mm] = s_ai[kk * 64 + mb + mm];
        }
#pragma unroll
        for (int nn = 0; nn < 4; nn++) {
            ull w1 = s_w1[kk * 64 + nn * 16 + tx];
            ull w2 = s_w2[kk * 64 + nn * 16 + tx];
#pragma unroll
            for (int mm = 0; mm < 4; mm++) {
                acc[mm][nn] = fma2(dur[mm], w1, acc[mm][nn]);  // (a*Wr, a*Wi)
                acc[mm][nn] = fma2(dui[mm], w2, acc[mm][nn]);  // (-b*Wi, b*Wr)
            }
        }
    }

#pragma unroll
    for (int mm = 0; mm < 4; mm++) {
        int m = m0 + mb + mm;
        if (m >= BT_) continue;
        size_t base = ((size_t)x * BT_ + m) * 1024 + n0;
#pragma unroll
        for (int nn = 0; nn < 4; nn++) {
            float re, im; unpack2(acc[mm][nn], re, im);
            d_Mre[base + nn * 16 + tx] = re;
            d_Mim[base + nn * 16 + tx] = im;
        }
    }
}

// Sequential scan: z_{t+1} = (I + Meff_t) z_t. One CTA per (x,b) chain.
__global__ void __launch_bounds__(128) k_scan() {
    __shared__ float2 sz[H_];
    __shared__ float2 zbuf[H_][32];
    int x = blockIdx.x & 127, b = blockIdx.x >> 7;
    int tid = threadIdx.x;
    int i = tid >> 2, jg = tid & 3;

    if (tid < H_) {
        float2 z0v = d_zinit[(x * B_ + b) * H_ + tid];
        sz[tid] = z0v;
        zbuf[tid][0] = z0v;
    }
    __syncthreads();

    size_t mbase = ((size_t)x * BT_ + (size_t)b * TM1) * 1024 + i * H_ + jg * 8;
    float4 cr0 = *(const float4*)(d_Mre + mbase);
    float4 cr1 = *(const float4*)(d_Mre + mbase + 4);
    float4 ci0 = *(const float4*)(d_Mim + mbase);
    float4 ci1 = *(const float4*)(d_Mim + mbase + 4);

    for (int t = 0; t < TM1; t++) {
        float4 nr0 = cr0, nr1 = cr1, ni0 = ci0, ni1 = ci1;
        if (t + 1 < TM1) {
            size_t nb = mbase + (size_t)(t + 1) * 1024;
            nr0 = *(const float4*)(d_Mre + nb);
            nr1 = *(const float4*)(d_Mre + nb + 4);
            ni0 = *(const float4*)(d_Mim + nb);
            ni1 = *(const float4*)(d_Mim + nb + 4);
        }
        float mr[8] = {cr0.x, cr0.y, cr0.z, cr0.w, cr1.x, cr1.y, cr1.z, cr1.w};
        float mi[8] = {ci0.x, ci0.y, ci0.z, ci0.w, ci1.x, ci1.y, ci1.z, ci1.w};

        float2 zold = sz[i];
        ull acc = 0;
#pragma unroll
        for (int s = 0; s < 8; s++) {
            float2 zv = sz[jg * 8 + s];
            acc = fma2(pack2(mr[s], mr[s]), pack2(zv.x, zv.y), acc);
            acc = fma2(pack2(mi[s], mi[s]), pack2(-zv.y, zv.x), acc);
        }
        float re, im; unpack2(acc, re, im);
        re += __shfl_xor_sync(0xFFFFFFFFu, re, 1);
        re += __shfl_xor_sync(0xFFFFFFFFu, re, 2);
        im += __shfl_xor_sync(0xFFFFFFFFu, im, 1);
        im += __shfl_xor_sync(0xFFFFFFFFu, im, 2);
        __syncthreads();
        if (jg == 0) {
            float2 zn = make_float2(zold.x + re, zold.y + im);
            sz[i] = zn;
            zbuf[i][(t + 1) & 31] = zn;
        }
        __syncthreads();

        if (((t + 1) & 31) == 31) {
            int tbase = (t + 1) - 31;
            int fi = tid >> 2, ts = (tid & 3) * 8;
            size_t obase = (((size_t)(b * H_ + fi)) * X_ + x) * T_ + tbase + ts;
#pragma unroll
            for (int q = 0; q < 8; q++) {
                float2 v = zbuf[fi][ts + q];
                d_zr[obase + q] = v.x;
                d_zi[obase + q] = v.y;
            }
        }

        cr0 = nr0; cr1 = nr1; ci0 = ni0; ci1 = ni1;
    }
}

// u[b,i,x,t] = (1/128)(-1)^x sum_k ( zr*Ex + zi*(-Ey) ), SoA planes.
__global__ void __launch_bounds__(256) k_out(float* __restrict__ out) {
    __shared__ float szr[X_ * 34];
    __shared__ float szi[X_ * 34];
    int t0 = blockIdx.x * 32;
    int bi = blockIdx.y;
    int tid = threadIdx.x;

    for (int e = tid; e < X_ * 32; e += 256) {
        int k = e >> 5, tl = e & 31;
        size_t g = ((size_t)bi * X_ + k) * T_ + t0 + tl;
        szr[k * 34 + tl] = d_zr[g];
        szi[k * 34 + tl] = d_zi[g];
    }
    __syncthreads();

    int x = tid & 127, th = tid >> 7;
    int tb = th * 16;
    ull acc[8];
#pragma unroll
    for (int p = 0; p < 8; p++) acc[p] = 0;

#pragma unroll 2
    for (int k = 0; k < X_; k++) {
        float2 e2 = d_E[k * X_ + x];
        ull ex = pack2(e2.x, e2.x);
        ull ey = pack2(-e2.y, -e2.y);
        const ull* rr = (const ull*)(szr + k * 34 + tb);
        const ull* ri = (const ull*)(szi + k * 34 + tb);
#pragma unroll
        for (int p = 0; p < 8; p++) {
            acc[p] = fma2(ex, rr[p], acc[p]);
            acc[p] = fma2(ey, ri[p], acc[p]);
        }
    }
    float r[16];
#pragma unroll
    for (int p = 0; p < 8; p++) unpack2(acc[p], r[2 * p], r[2 * p + 1]);
    size_t ob = ((size_t)bi * X_ + x) * T_ + t0 + tb;
#pragma unroll
    for (int q = 0; q < 4; q++)
        *(float4*)(out + ob + 4 * q) = make_float4(r[4*q], r[4*q+1], r[4*q+2], r[4*q+3]);
}

extern "C" void kernel_launch(void* const* d_in, const int* in_sizes, int n_in,
                              void* d_out, int out_size) {
    const float* z0 = (const float*)d_in[0];
    const float* xi = (const float*)d_in[1];
    // d_in[2] = A (cancels exactly in the t-difference dX)
    const float* Gw = (const float*)d_in[3];
    const float* Wr = (const float*)d_in[4];
    const float* Wi = (const float*)d_in[5];
    float* out = (float*)d_out;

    const int dx_smem = SDX_ULL * 8;            // ~206 KB
    cudaFuncSetAttribute(k_dX, cudaFuncAttributeMaxDynamicSharedMemorySize, dx_smem);
    cudaFuncSetAttribute(k_meff, cudaFuncAttributeMaxDynamicSharedMemorySize, 65536);

    k_twiddle<<<X_, X_>>>();
    k_g2<<<(B_ * H_ * F_ * X_) / 256, 256>>>(z0, Gw);
    k_zinit<<<B_ * H_, X_>>>(z0);
    k_dX<<<dim3(4, B_ * H_), 256, dx_smem>>>(xi);
    k_meff<<<dim3(16, 32, X_), 256, 65536>>>(Wr, Wi);
    k_scan<<<B_ * X_, 128>>>();
    k_out<<<dim3(T_ / 32, B_ * H_), 256>>>(out);
}

// round 6
// speedup vs baseline: 1.2965x; 1.2965x over previous
#include <cuda_runtime.h>
#include <cuda_bf16.h>
#include <cstdint>
#include <cstddef>

#define B_   8
#define H_   32
#define F_   8
#define X_   128
#define T_   256
#define TM1  255
#define BT_  2040   // B_*TM1

typedef unsigned long long ull;

// ---------- packed f32x2 helpers (FFMA2 only reachable via PTX) ----------
__device__ __forceinline__ ull pack2(float x, float y) {
    ull r; asm("mov.b64 %0,{%1,%2};" : "=l"(r) : "f"(x), "f"(y)); return r;
}
__device__ __forceinline__ void unpack2(ull v, float& x, float& y) {
    asm("mov.b64 {%0,%1},%2;" : "=f"(x), "=f"(y) : "l"(v));
}
__device__ __forceinline__ ull fma2(ull a, ull b, ull c) {
    ull r; asm("fma.rn.f32x2 %0,%1,%2,%3;" : "=l"(r) : "l"(a), "l"(b), "l"(c)); return r;
}

// ---------- static scratch ----------
__device__ __align__(16) float  d_G2[B_ * H_ * F_ * X_];          // [b][c][f][x]
__device__ __align__(16) float2 d_D[X_ * X_];                     // [k][x] fwd twiddles
__device__ __align__(16) float2 d_E[X_ * X_];                     // [k][x] inv twiddles (1/128)
__device__ __align__(16) float2 d_dX[(size_t)X_ * TM1 * B_ * H_]; // [k][t][b][c]
__device__ __align__(16) float2 d_zinit[X_ * B_ * H_];            // [k][b][i]
__device__ __align__(16) float  d_Mre[(size_t)X_ * BT_ * 1024];   // [x][m=b*255+t][i*32+j]
__device__ __align__(16) float  d_Mim[(size_t)X_ * BT_ * 1024];
__device__ __align__(16) float  d_zr[(size_t)B_ * H_ * X_ * T_];  // [b][i][k][t] re plane
__device__ __align__(16) float  d_zi[(size_t)B_ * H_ * X_ * T_];  // [b][i][k][t] im plane

// shifted-fwd: S[k] = sum_x h[x] (-1)^x e^{-2pi i k x/128}
// inverse:     u[x] = (1/128)(-1)^x sum_k Re( z[k] e^{+2pi i k x/128} )
__global__ void k_twiddle() {
    int k = blockIdx.x, x = threadIdx.x;
    float s, c;
    sincospif((float)(k * x) * (1.0f / 64.0f), &s, &c);
    float sg = (x & 1) ? -1.0f : 1.0f;
    d_D[k * X_ + x] = make_float2(sg * c, -sg * s);
    d_E[k * X_ + x] = make_float2(sg * c * (1.0f / 128.0f), sg * s * (1.0f / 128.0f));
}

// G2[b][c][f][x] = sum_h Gw[c][f][h] * z0[b][h][x]
__global__ void k_g2(const float* __restrict__ z0, const float* __restrict__ Gw) {
    int idx = blockIdx.x * blockDim.x + threadIdx.x;
    int x = idx & 127, f = (idx >> 7) & 7, c = (idx >> 10) & 31, b = idx >> 15;
    const float* gw = Gw + (c * F_ + f) * H_;
    const float* zp = z0 + b * H_ * X_ + x;
    float acc = 0.0f;
#pragma unroll
    for (int h = 0; h < H_; h++) acc += gw[h] * zp[h * X_];
    d_G2[idx] = acc;
}

// z_init[k][b][i] = shifted-DFT_x( z0[b][i][:] )
__global__ void k_zinit(const float* __restrict__ z0) {
    int b = blockIdx.x >> 5, i = blockIdx.x & 31, k = threadIdx.x;
    const float* zp = z0 + (b * H_ + i) * X_;
    const ull* Dr = (const ull*)d_D + k * X_;
    ull acc = 0;
#pragma unroll 4
    for (int x = 0; x < X_; x++) {
        float h = zp[x];
        acc = fma2(pack2(h, h), Dr[x], acc);
    }
    float2 r; unpack2(acc, r.x, r.y);
    d_zinit[(k * B_ + b) * H_ + i] = r;
}

// dX[k][t][b][ch] = DFTshift_x( sum_f G2[b][ch][f][x]*(xi[...t+1]-xi[...t]) )
// Grid (4 t-chunks, 256 bc, 2 k-halves). Each CTA: 64 k x 64 t.
// smem: D half (64x129 ull, conflict-free), h floats (64x129), G2 slice.
// Thread (tq=tid&7, kq=tid>>3): 2k x 8t tile -> 16 fma2 / (2 LDS64 + 8 LDS32) per x.
#define SDX_D    0
#define SDX_H    8256                  // ull offset; sH is float*
#define SDX_G    (SDX_H + 4128)        // 8256 floats = 4128 ull
#define SDX_ULL  (SDX_G + 512)         // sG: 1024 floats
__global__ void __launch_bounds__(256) k_dX(const float* __restrict__ xi) {
    extern __shared__ ull sm[];
    ull*   sD = sm + SDX_D;            // [k_local][x] stride 129
    float* sH = (float*)(sm + SDX_H);  // [t][x] stride 129
    float* sG = (float*)(sm + SDX_G);  // [f][x]
    int tid = threadIdx.x;
    int t0 = blockIdx.x * 64;
    int b = blockIdx.y >> 5, ch = blockIdx.y & 31;
    int kh = blockIdx.z;               // k-half: k in [kh*64, kh*64+64)
    int tn = min(64, TM1 - t0);

    const ull* pD = (const ull*)d_D + (size_t)kh * 64 * X_;
    for (int e = tid; e < 64 * 128; e += 256) {
        int kl = e >> 7, x = e & 127;
        sD[kl * 129 + x] = pD[e];
    }
    for (int e = tid; e < F_ * X_; e += 256)
        sG[e] = d_G2[(b * H_ + ch) * F_ * X_ + e];
    __syncthreads();

    // phase A: h[t][x] = sum_f G2*(xi[t+1]-xi[t])
    for (int e = tid; e < X_ * 64; e += 256) {
        int x = e >> 6, t = e & 63;
        float acc = 0.0f;
        if (t < tn) {
#pragma unroll
            for (int f = 0; f < F_; f++) {
                const float* xp = xi + (((size_t)(b * F_ + f) * X_ + x) * T_) + t0 + t;
                acc += sG[f * X_ + x] * (xp[1] - xp[0]);
            }
        }
        sH[t * 129 + x] = acc;
    }
    __syncthreads();

    // phase B: register-tiled DFT over the 64-k half
    int tq = tid & 7, kq = tid >> 3;   // kq in [0,32): k_local = kq*2+c
    ull acc[2][8];
#pragma unroll
    for (int c = 0; c < 2; c++)
#pragma unroll
        for (int s = 0; s < 8; s++) acc[c][s] = 0;

#pragma unroll 2
    for (int x = 0; x < X_; x++) {
        ull dv[2];
#pragma unroll
        for (int c = 0; c < 2; c++) dv[c] = sD[(kq * 2 + c) * 129 + x];
        ull hh[8];
#pragma unroll
        for (int s = 0; s < 8; s++) {
            float h = sH[(tq + 8 * s) * 129 + x];
            hh[s] = pack2(h, h);
        }
#pragma unroll
        for (int s = 0; s < 8; s++)
#pragma unroll
            for (int c = 0; c < 2; c++) acc[c][s] = fma2(hh[s], dv[c], acc[c][s]);
    }

#pragma unroll
    for (int c = 0; c < 2; c++) {
        int k = kh * 64 + kq * 2 + c;
#pragma unroll
        for (int s = 0; s < 8; s++) {
            int t = t0 + tq + 8 * s;
            if (t >= TM1) continue;
            float re, im; unpack2(acc[c][s], re, im);
            d_dX[((size_t)(k * TM1 + t) * B_ + b) * H_ + ch] = make_float2(re, im);
        }
    }
}

// Meff[x][m][i*32+j] = sum_c dx[b,x,t,c]*W[x,i,c,j] (complex), m=b*255+t.
// GEMM per x: M=2040, N=1024, K=32. Tile 64m x 64n, 256 thr, 4x4/thread.
// (round-4 form: 32KB static smem, packing in registers on the idle ALU pipe)
__global__ void __launch_bounds__(256) k_meff(const float* __restrict__ Wr,
                                              const float* __restrict__ Wi) {
    __shared__ float2 s_dx[32 * 64];   // [k][m] 16KB
    __shared__ float2 s_w[32 * 64];    // [k][n] 16KB
    int x  = blockIdx.z;
    int m0 = blockIdx.y * 64;
    int n0 = blockIdx.x * 64;

    for (int e = threadIdx.x; e < 64 * 32; e += 256) {
        int ml = e >> 5, kk = e & 31;
        int m = m0 + ml;
        float2 v = make_float2(0.0f, 0.0f);
        if (m < BT_) {
            int bb = m / TM1, tt = m - bb * TM1;
            v = d_dX[((size_t)(x * TM1 + tt) * B_ + bb) * H_ + kk];
        }
        s_dx[kk * 64 + ml] = v;
    }
    for (int e = threadIdx.x; e < 32 * 64; e += 256) {
        int kk = e >> 6, nn = e & 63;
        int n = n0 + nn;
        int i = n >> 5, j = n & 31;
        size_t g = (((size_t)x * H_ + i) * H_ + kk) * H_ + j;
        s_w[kk * 64 + nn] = make_float2(Wr[g], Wi[g]);
    }
    __syncthreads();

    int tx = threadIdx.x & 15, ty = threadIdx.x >> 4;
    int mb = ty * 4;
    ull acc[4][4];
#pragma unroll
    for (int mm = 0; mm < 4; mm++)
#pragma unroll
        for (int nn = 0; nn < 4; nn++) acc[mm][nn] = 0;

#pragma unroll 4
    for (int kk = 0; kk < 32; kk++) {
        ull dur[4], dui[4];
#pragma unroll
        for (int mm = 0; mm < 4; mm++) {
            float2 a = s_dx[kk * 64 + mb + mm];
            dur[mm] = pack2(a.x, a.x);
            dui[mm] = pack2(a.y, a.y);
        }
#pragma unroll
        for (int nn = 0; nn < 4; nn++) {
            float2 w = s_w[kk * 64 + nn * 16 + tx];
            ull w1 = pack2(w.x, w.y);
            ull w2 = pack2(-w.y, w.x);
#pragma unroll
            for (int mm = 0; mm < 4; mm++) {
                acc[mm][nn] = fma2(dur[mm], w1, acc[mm][nn]);  // (a*Wr, a*Wi)
                acc[mm][nn] = fma2(dui[mm], w2, acc[mm][nn]);  // (-b*Wi, b*Wr)
            }
        }
    }

#pragma unroll
    for (int mm = 0; mm < 4; mm++) {
        int m = m0 + mb + mm;
        if (m >= BT_) continue;
        size_t base = ((size_t)x * BT_ + m) * 1024 + n0;
#pragma unroll
        for (int nn = 0; nn < 4; nn++) {
            float re, im; unpack2(acc[mm][nn], re, im);
            d_Mre[base + nn * 16 + tx] = re;
            d_Mim[base + nn * 16 + tx] = im;
        }
    }
}

// Sequential scan: z_{t+1} = (I + Meff_t) z_t. One CTA per (x,b) chain.
__global__ void __launch_bounds__(128) k_scan() {
    __shared__ float2 sz[H_];
    __shared__ float2 zbuf[H_][32];
    int x = blockIdx.x & 127, b = blockIdx.x >> 7;
    int tid = threadIdx.x;
    int i = tid >> 2, jg = tid & 3;

    if (tid < H_) {
        float2 z0v = d_zinit[(x * B_ + b) * H_ + tid];
        sz[tid] = z0v;
        zbuf[tid][0] = z0v;
    }
    __syncthreads();

    size_t mbase = ((size_t)x * BT_ + (size_t)b * TM1) * 1024 + i * H_ + jg * 8;
    float4 cr0 = *(const float4*)(d_Mre + mbase);
    float4 cr1 = *(const float4*)(d_Mre + mbase + 4);
    float4 ci0 = *(const float4*)(d_Mim + mbase);
    float4 ci1 = *(const float4*)(d_Mim + mbase + 4);

    for (int t = 0; t < TM1; t++) {
        float4 nr0 = cr0, nr1 = cr1, ni0 = ci0, ni1 = ci1;
        if (t + 1 < TM1) {
            size_t nb = mbase + (size_t)(t + 1) * 1024;
            nr0 = *(const float4*)(d_Mre + nb);
            nr1 = *(const float4*)(d_Mre + nb + 4);
            ni0 = *(const float4*)(d_Mim + nb);
            ni1 = *(const float4*)(d_Mim + nb + 4);
        }
        float mr[8] = {cr0.x, cr0.y, cr0.z, cr0.w, cr1.x, cr1.y, cr1.z, cr1.w};
        float mi[8] = {ci0.x, ci0.y, ci0.z, ci0.w, ci1.x, ci1.y, ci1.z, ci1.w};

        float2 zold = sz[i];
        ull acc = 0;
#pragma unroll
        for (int s = 0; s < 8; s++) {
            float2 zv = sz[jg * 8 + s];
            acc = fma2(pack2(mr[s], mr[s]), pack2(zv.x, zv.y), acc);
            acc = fma2(pack2(mi[s], mi[s]), pack2(-zv.y, zv.x), acc);
        }
        float re, im; unpack2(acc, re, im);
        re += __shfl_xor_sync(0xFFFFFFFFu, re, 1);
        re += __shfl_xor_sync(0xFFFFFFFFu, re, 2);
        im += __shfl_xor_sync(0xFFFFFFFFu, im, 1);
        im += __shfl_xor_sync(0xFFFFFFFFu, im, 2);
        __syncthreads();
        if (jg == 0) {
            float2 zn = make_float2(zold.x + re, zold.y + im);
            sz[i] = zn;
            zbuf[i][(t + 1) & 31] = zn;
        }
        __syncthreads();

        if (((t + 1) & 31) == 31) {
            int tbase = (t + 1) - 31;
            int fi = tid >> 2, ts = (tid & 3) * 8;
            size_t obase = (((size_t)(b * H_ + fi)) * X_ + x) * T_ + tbase + ts;
#pragma unroll
            for (int q = 0; q < 8; q++) {
                float2 v = zbuf[fi][ts + q];
                d_zr[obase + q] = v.x;
                d_zi[obase + q] = v.y;
            }
        }

        cr0 = nr0; cr1 = nr1; ci0 = ni0; ci1 = ni1;
    }
}

// u[b,i,x,t] = (1/128)(-1)^x sum_k ( zr*Ex + zi*(-Ey) ), SoA planes.
__global__ void __launch_bounds__(256) k_out(float* __restrict__ out) {
    __shared__ float szr[X_ * 34];
    __shared__ float szi[X_ * 34];
    int t0 = blockIdx.x * 32;
    int bi = blockIdx.y;
    int tid = threadIdx.x;

    for (int e = tid; e < X_ * 32; e += 256) {
        int k = e >> 5, tl = e & 31;
        size_t g = ((size_t)bi * X_ + k) * T_ + t0 + tl;
        szr[k * 34 + tl] = d_zr[g];
        szi[k * 34 + tl] = d_zi[g];
    }
    __syncthreads();

    int x = tid & 127, th = tid >> 7;
    int tb = th * 16;
    ull acc[8];
#pragma unroll
    for (int p = 0; p < 8; p++) acc[p] = 0;

#pragma unroll 2
    for (int k = 0; k < X_; k++) {
        float2 e2 = d_E[k * X_ + x];
        ull ex = pack2(e2.x, e2.x);
        ull ey = pack2(-e2.y, -e2.y);
        const ull* rr = (const ull*)(szr + k * 34 + tb);
        const ull* ri = (const ull*)(szi + k * 34 + tb);
#pragma unroll
        for (int p = 0; p < 8; p++) {
            acc[p] = fma2(ex, rr[p], acc[p]);
            acc[p] = fma2(ey, ri[p], acc[p]);
        }
    }
    float r[16];
#pragma unroll
    for (int p = 0; p < 8; p++) unpack2(acc[p], r[2 * p], r[2 * p + 1]);
    size_t ob = ((size_t)bi * X_ + x) * T_ + t0 + tb;
#pragma unroll
    for (int q = 0; q < 4; q++)
        *(float4*)(out + ob + 4 * q) = make_float4(r[4*q], r[4*q+1], r[4*q+2], r[4*q+3]);
}

extern "C" void kernel_launch(void* const* d_in, const int* in_sizes, int n_in,
                              void* d_out, int out_size) {
    const float* z0 = (const float*)d_in[0];
    const float* xi = (const float*)d_in[1];
    // d_in[2] = A (cancels exactly in the t-difference dX)
    const float* Gw = (const float*)d_in[3];
    const float* Wr = (const float*)d_in[4];
    const float* Wi = (const float*)d_in[5];
    float* out = (float*)d_out;

    const int dx_smem = SDX_ULL * 8;            // ~103 KB -> 2 CTAs/SM
    cudaFuncSetAttribute(k_dX, cudaFuncAttributeMaxDynamicSharedMemorySize, dx_smem);

    k_twiddle<<<X_, X_>>>();
    k_g2<<<(B_ * H_ * F_ * X_) / 256, 256>>>(z0, Gw);
    k_zinit<<<B_ * H_, X_>>>(z0);
    k_dX<<<dim3(4, 256, 2), 256, dx_smem>>>(xi);
    k_meff<<<dim3(16, 32, X_), 256>>>(Wr, Wi);
    k_scan<<<B_ * X_, 128>>>();
    k_out<<<dim3(T_ / 32, B_ * H_), 256>>>(out);
}